// round 3
// baseline (speedup 1.0000x reference)
#include <cuda_runtime.h>
#include <math.h>

#define D        64
#define NC       16
#define NS       136
#define NSP      160          // padded state count (5*32)
#define NITEMS   5120         // 512 * 10
#define TPB      256
#define WPB      8
#define IPW      2            // items per warp
#define NB       (NITEMS / (WPB * IPW))   // 320 blocks

__device__ double       g_partial[NB];
__device__ unsigned int g_count;   // zero-init; last block resets each launch

__global__ __launch_bounds__(TPB)
void latent_fused(const float* __restrict__ z, const float* __restrict__ mu,
                  const float* __restrict__ pi, const int* __restrict__ A,
                  const int* __restrict__ B, float* __restrict__ out) {
    __shared__ float  s_mu[D * NC];       // [d][c]
    __shared__ float  s_G[NC * NC];       // gram
    __shared__ float4 s_c4[NSP];          // {gbb, cab, rinv, sd}
    __shared__ float  s_lc[NSP];
    __shared__ int    s_ab[NSP];          // a | (b<<8)
    __shared__ float  s_red[TPB];
    __shared__ float  s_dz[WPB][NC];
    __shared__ float  s_z[WPB][D];
    __shared__ double s_wsum[WPB];
    __shared__ double s_fin[TPB];
    __shared__ int    s_islast;

    const float LOG2PI = 1.8378770664093453f;
    const float BASE   = -32.0f * LOG2PI;     // -0.5*d*log(2pi)

    int t = threadIdx.x;
    int w = t >> 5, lane = t & 31;

    // ---- stage mu + state meta ----
    #pragma unroll
    for (int i = t; i < D * NC; i += TPB) s_mu[i] = mu[i];
    float piv = 0.f; int sa = 0, sb = 0;
    if (t < NS) { sa = A[t]; sb = B[t]; piv = pi[t]; }
    s_red[t] = (t < NS) ? __expf(piv) : 0.f;
    __syncthreads();

    // ---- gram matrix: thread t -> pair (a=t&15, b=t>>4), 64 FMA ----
    {
        int ga = t & 15, gb = t >> 4;
        float g0 = 0.f, g1 = 0.f;
        #pragma unroll
        for (int d = 0; d < D; d += 2) {
            g0 = fmaf(s_mu[d * NC + ga],       s_mu[d * NC + gb],       g0);
            g1 = fmaf(s_mu[(d + 1) * NC + ga], s_mu[(d + 1) * NC + gb], g1);
        }
        s_G[t] = g0 + g1;
    }
    __syncthreads();

    // ---- per-state constants (only once per block, transcendentals hoisted) ----
    if (t < NSP) {
        // softmax(pi) denominator: per-warp redundant reduce (warps 0..4)
        float ps = 0.f;
        #pragma unroll
        for (int i = 0; i < TPB / 32; i++) ps += s_red[lane + 32 * i];
        #pragma unroll
        for (int off = 16; off; off >>= 1)
            ps += __shfl_xor_sync(0xffffffffu, ps, off);

        if (t < NS) {
            float gaa = s_G[sa * NC + sa];
            float gbb = s_G[sb * NC + sb];
            float gab = s_G[sb * NC + sa];
            float invsig = fmaf(-2.f, gab, gbb) + gaa;   // exact 0 on diagonal
            float cab    = gbb - gab;                    // exact 0 on diagonal
            float lpi    = __logf(__expf(piv) / ps + 1e-12f);
            float rinv, sd, lc;
            if (invsig == 0.f) {
                rinv = 0.f; sd = 0.f;
                lc = BASE + lpi - __logf(1e-12f);        // cancels runtime log(0+1e-12)
            } else {
                rinv = 1.0f / invsig;
                sd   = sqrtf(invsig + 1e-12f);
                lc   = BASE + lpi + 0.5f * (LOG2PI - __logf(invsig + 1e-12f));
            }
            s_c4[t] = make_float4(gbb, cab, rinv, sd);
            s_lc[t] = lc;
            s_ab[t] = sa | (sb << 8);
        } else {
            // padding: produces val ~ -1e30 -> vanishes in logsumexp, no NaN
            s_c4[t] = make_float4(0.f, 0.f, 0.f, 0.f);
            s_lc[t] = -1e30f;
            s_ab[t] = 0;
        }
    }
    __syncthreads();

    // ---- items: IPW per warp ----
    double dsum = 0.0;
    int item0 = (blockIdx.x * WPB + w) * IPW;
    int h = lane >> 4, c = lane & 15;

    #pragma unroll
    for (int j = 0; j < IPW; j++) {
        int item = item0 + j;
        const float2* zp = (const float2*)(z + item * D);
        float2 zv = zp[lane];
        __syncwarp();
        s_z[w][2 * lane]     = zv.x;
        s_z[w][2 * lane + 1] = zv.y;

        float zn = fmaf(zv.x, zv.x, zv.y * zv.y);
        #pragma unroll
        for (int off = 16; off; off >>= 1)
            zn += __shfl_xor_sync(0xffffffffu, zn, off);
        __syncwarp();

        // split dot: lane (c,h) does dims [h*32, h*32+32)
        {
            float a0 = 0.f, a1 = 0.f;
            const float* zr = s_z[w] + h * 32;
            const float* mr = s_mu + h * 32 * NC + c;
            #pragma unroll
            for (int i = 0; i < 32; i += 2) {
                a0 = fmaf(zr[i],     mr[i * NC],       a0);
                a1 = fmaf(zr[i + 1], mr[(i + 1) * NC], a1);
            }
            float dv = a0 + a1;
            dv += __shfl_xor_sync(0xffffffffu, dv, 16);
            if (lane < NC) s_dz[w][lane] = dv;
        }
        __syncwarp();

        // 5 states per lane, branchless
        float v[5];
        #pragma unroll
        for (int k = 0; k < 5; k++) {
            int s  = lane + 32 * k;
            int ab = s_ab[s];
            float4 cc = s_c4[s];             // {gbb, cab, rinv, sd}
            float dzA = s_dz[w][ab & 255];
            float dzB = s_dz[w][ab >> 8];
            float sq    = fmaf(-2.f, dzB, zn) + cc.x;
            float dot12 = (dzB - dzA) - cc.y;
            float mu_   = -dot12 * cc.z;
            float t2    = fmaf(dot12, mu_, sq);          // = -( _t )
            float u1    = (1.f - mu_) * cc.w;
            float u0    = -mu_ * cc.w;
            float cdfd  = normcdff(u1) - normcdff(u0);
            v[k] = fmaf(-0.5f, t2, s_lc[s]) + __logf(cdfd + 1e-12f);
        }
        float m = fmaxf(fmaxf(fmaxf(v[0], v[1]), fmaxf(v[2], v[3])), v[4]);
        float acc = __expf(v[0] - m) + __expf(v[1] - m) + __expf(v[2] - m)
                  + __expf(v[3] - m) + __expf(v[4] - m);

        #pragma unroll
        for (int off = 16; off; off >>= 1) {
            float m2 = __shfl_xor_sync(0xffffffffu, m,   off);
            float a2 = __shfl_xor_sync(0xffffffffu, acc, off);
            float M  = fmaxf(m, m2);
            acc = acc * __expf(m - M) + a2 * __expf(m2 - M);
            m = M;
        }
        if (lane == 0) dsum += (double)(m + __logf(acc));
    }

    if (lane == 0) s_wsum[w] = dsum;
    __syncthreads();

    // ---- deterministic finalize in last block ----
    if (t == 0) {
        double ssum = 0.0;
        #pragma unroll
        for (int i = 0; i < WPB; i++) ssum += s_wsum[i];
        g_partial[blockIdx.x] = ssum;
        __threadfence();
        unsigned int tick = atomicAdd(&g_count, 1u);
        s_islast = (tick == NB - 1u);
    }
    __syncthreads();

    if (s_islast) {
        double vv = 0.0;
        for (int i = t; i < NB; i += TPB) vv += g_partial[i];
        s_fin[t] = vv;
        __syncthreads();
        #pragma unroll
        for (int off = TPB / 2; off > 0; off >>= 1) {
            if (t < off) s_fin[t] += s_fin[t + off];
            __syncthreads();
        }
        if (t == 0) {
            out[0] = (float)(s_fin[0] / (double)NITEMS);
            g_count = 0;
        }
    }
}

extern "C" void kernel_launch(void* const* d_in, const int* in_sizes, int n_in,
                              void* d_out, int out_size) {
    const float* z  = (const float*)d_in[0];
    const float* mu = (const float*)d_in[1];
    const float* pi = (const float*)d_in[2];
    const int*   A  = (const int*)d_in[3];
    const int*   B  = (const int*)d_in[4];
    float* out = (float*)d_out;
    (void)in_sizes; (void)n_in; (void)out_size;

    latent_fused<<<NB, TPB>>>(z, mu, pi, A, B, out);
}

// round 6
// speedup vs baseline: 1.6943x; 1.6943x over previous
#include <cuda_runtime.h>
#include <math.h>

#define D        64
#define NC       16
#define NS       136
#define NSP      160          // padded (5*32)
#define NITEMS   5120
#define TPB      256
#define WPB      8            // 1 item per warp
#define NB       (NITEMS / WPB)   // 640 blocks
#define PITCH    68           // muT row pitch (floats); 272B, 16B-aligned

__device__ double       g_partial[NB];
__device__ unsigned int g_count;

__device__ __forceinline__ float fast_ndtr(float x) {
    // Phi(x) ~= 0.5*(1 + tanh(0.79788456*(x + 0.044715*x^3))), |err| <~ 2e-4
    float u = 0.79788456f * fmaf(0.044715f, x * x * x, x);
    float t;
    asm("tanh.approx.f32 %0, %1;" : "=f"(t) : "f"(u));
    return fmaf(0.5f, t, 0.5f);
}

__global__ __launch_bounds__(TPB)
void latent_fused(const float* __restrict__ z, const float* __restrict__ mu,
                  const float* __restrict__ pi, const int* __restrict__ A,
                  const int* __restrict__ B, float* __restrict__ out) {
    __shared__ __align__(16) float s_muT[NC * PITCH];   // [c][d], pitch 68
    __shared__ float  s_G[NC * NC];
    __shared__ float4 s_c4[NSP];          // {gbb, cab, rinv, sd}
    __shared__ float2 s_cc[NSP];          // {lc, ab-as-int}
    __shared__ float  s_red[TPB];
    __shared__ float4 s_z4[WPB][16];
    __shared__ float  s_dz[WPB][NC];
    __shared__ double s_wsum[WPB];
    __shared__ double s_fin[TPB];
    __shared__ int    s_islast;

    const float LOG2PI = 1.8378770664093453f;
    const float BASE   = -32.0f * LOG2PI;

    int t = threadIdx.x, w = t >> 5, lane = t & 31;
    int item = blockIdx.x * WPB + w;

    // ---- early z load (lanes 0..15 of each warp, float4) ----
    const float4* zp4 = (const float4*)(z + item * D);
    float4 zv = make_float4(0.f, 0.f, 0.f, 0.f);
    if (lane < 16) zv = zp4[lane];

    // ---- stage mu transposed + state meta ----
    #pragma unroll
    for (int i = t; i < D * NC; i += TPB) {
        int d = i >> 4, c = i & 15;
        s_muT[c * PITCH + d] = mu[i];
    }
    float piv = 0.f; int sa = 0, sb = 0;
    if (t < NS) { sa = A[t]; sb = B[t]; piv = pi[t]; }
    s_red[t] = (t < NS) ? __expf(piv) : 0.f;
    if (lane < 16) s_z4[w][lane] = zv;
    __syncthreads();

    // ---- gram: thread t = (ga = t&15, gb = t>>4) ----
    {
        int ga = t & 15, gb = t >> 4;
        const float4* ra = (const float4*)(s_muT + ga * PITCH);
        const float4* rb = (const float4*)(s_muT + gb * PITCH);
        float g0 = 0.f, g1 = 0.f;
        #pragma unroll
        for (int i = 0; i < 16; i++) {
            float4 x = ra[i], y = rb[i];
            g0 = fmaf(x.x, y.x, g0); g0 = fmaf(x.y, y.y, g0);
            g1 = fmaf(x.z, y.z, g1); g1 = fmaf(x.w, y.w, g1);
        }
        s_G[t] = g0 + g1;
    }
    __syncthreads();

    // ---- per-state constants (transcendentals hoisted) ----
    if (t < NSP) {
        float ps = 0.f;
        #pragma unroll
        for (int i = 0; i < TPB / 32; i++) ps += s_red[lane + 32 * i];
        #pragma unroll
        for (int off = 16; off; off >>= 1)
            ps += __shfl_xor_sync(0xffffffffu, ps, off);

        if (t < NS) {
            float gaa = s_G[sa * NC + sa];
            float gbb = s_G[sb * NC + sb];
            float gab = s_G[sb * NC + sa];
            float invsig = fmaf(-2.f, gab, gbb) + gaa;   // exact 0 when sa==sb
            float cab    = gbb - gab;
            float lpi    = __logf(__expf(piv) / ps + 1e-12f);
            float rinv, sd, lc;
            if (invsig == 0.f) {
                rinv = 0.f; sd = 0.f;
                lc = BASE + lpi - __logf(1e-12f);        // cancels runtime log(0+1e-12)
            } else {
                rinv = 1.0f / invsig;
                sd   = sqrtf(invsig + 1e-12f);
                lc   = BASE + lpi + 0.5f * (LOG2PI - __logf(invsig + 1e-12f));
            }
            s_c4[t] = make_float4(gbb, cab, rinv, sd);
            s_cc[t] = make_float2(lc, __int_as_float(sa | (sb << 8)));
        } else {
            s_c4[t] = make_float4(0.f, 0.f, 0.f, 0.f);
            s_cc[t] = make_float2(-1e30f, __int_as_float(0));
        }
    }

    // ---- zn = |z|^2 (butterfly; lanes >=16 contribute 0) ----
    float zn = fmaf(zv.x, zv.x, fmaf(zv.y, zv.y, fmaf(zv.z, zv.z, zv.w * zv.w)));
    #pragma unroll
    for (int off = 16; off; off >>= 1)
        zn += __shfl_xor_sync(0xffffffffu, zn, off);
    __syncthreads();

    // ---- dot products: lane (c = lane&15, h = lane>>4) covers dims [h*32, h*32+32) ----
    int c = lane & 15, h = lane >> 4;
    {
        float a0 = 0.f, a1 = 0.f;
        const float4* mt = (const float4*)(s_muT + c * PITCH) + h * 8;
        const float4* zt = &s_z4[w][h * 8];
        #pragma unroll
        for (int i = 0; i < 8; i++) {
            float4 mm = mt[i], zz = zt[i];
            a0 = fmaf(mm.x, zz.x, a0); a0 = fmaf(mm.y, zz.y, a0);
            a1 = fmaf(mm.z, zz.z, a1); a1 = fmaf(mm.w, zz.w, a1);
        }
        float dv = a0 + a1;
        dv += __shfl_xor_sync(0xffffffffu, dv, 16);
        if (lane < NC) s_dz[w][lane] = dv;
    }
    __syncwarp();

    // ---- 5 states per lane, branchless ----
    float v[5];
    #pragma unroll
    for (int k = 0; k < 5; k++) {
        int s = lane + 32 * k;
        float4 cc = s_c4[s];              // {gbb, cab, rinv, sd}
        float2 c2 = s_cc[s];              // {lc, ab}
        int ab = __float_as_int(c2.y);
        float dzA = s_dz[w][ab & 255];
        float dzB = s_dz[w][ab >> 8];
        float sq    = fmaf(-2.f, dzB, zn) + cc.x;
        float dot12 = (dzB - dzA) - cc.y;
        float mu_   = -dot12 * cc.z;
        float t2    = fmaf(dot12, mu_, sq);              // = -_t
        float cdfd  = fast_ndtr((1.f - mu_) * cc.w) - fast_ndtr(-mu_ * cc.w);
        cdfd = fmaxf(cdfd, 0.f);
        v[k] = fmaf(-0.5f, t2, c2.x) + __logf(cdfd + 1e-12f);
    }
    float m = fmaxf(fmaxf(fmaxf(v[0], v[1]), fmaxf(v[2], v[3])), v[4]);
    float acc = __expf(v[0] - m) + __expf(v[1] - m) + __expf(v[2] - m)
              + __expf(v[3] - m) + __expf(v[4] - m);

    #pragma unroll
    for (int off = 16; off; off >>= 1) {
        float m2 = __shfl_xor_sync(0xffffffffu, m,   off);
        float a2 = __shfl_xor_sync(0xffffffffu, acc, off);
        float M  = fmaxf(m, m2);
        acc = acc * __expf(m - M) + a2 * __expf(m2 - M);
        m = M;
    }

    if (lane == 0) s_wsum[w] = (double)(m + __logf(acc));
    __syncthreads();

    // ---- deterministic last-block finalize ----
    if (t == 0) {
        double ssum = 0.0;
        #pragma unroll
        for (int i = 0; i < WPB; i++) ssum += s_wsum[i];
        g_partial[blockIdx.x] = ssum;
        __threadfence();
        unsigned int tick = atomicAdd(&g_count, 1u);
        s_islast = (tick == NB - 1u);
    }
    __syncthreads();

    if (s_islast) {
        double vv = 0.0;
        for (int i = t; i < NB; i += TPB) vv += g_partial[i];
        s_fin[t] = vv;
        __syncthreads();
        #pragma unroll
        for (int off = TPB / 2; off > 0; off >>= 1) {
            if (t < off) s_fin[t] += s_fin[t + off];
            __syncthreads();
        }
        if (t == 0) {
            out[0] = (float)(s_fin[0] / (double)NITEMS);
            g_count = 0;   // reset for next graph replay
        }
    }
}

extern "C" void kernel_launch(void* const* d_in, const int* in_sizes, int n_in,
                              void* d_out, int out_size) {
    const float* z  = (const float*)d_in[0];
    const float* mu = (const float*)d_in[1];
    const float* pi = (const float*)d_in[2];
    const int*   A  = (const int*)d_in[3];
    const int*   B  = (const int*)d_in[4];
    float* out = (float*)d_out;
    (void)in_sizes; (void)n_in; (void)out_size;

    latent_fused<<<NB, TPB>>>(z, mu, pi, A, B, out);
}

// round 7
// speedup vs baseline: 1.7198x; 1.0151x over previous
#include <cuda_runtime.h>
#include <math.h>

#define D        64
#define NC       16
#define NS       136
#define NSP      160          // padded (5*32)
#define NITEMS   5120
#define TPB      256
#define WPB      8            // 1 item per warp
#define NB       (NITEMS / WPB)   // 640 blocks
#define PITCH    68           // muT row pitch (floats)

__device__ double       g_partial[NB];
__device__ unsigned int g_count;

__device__ __forceinline__ float fast_ndtr(float x) {
    // Phi(x) ~= 0.5*(1 + tanh(0.79788456*(x + 0.044715*x^3)))
    float u = 0.79788456f * fmaf(0.044715f, x * x * x, x);
    float t;
    asm("tanh.approx.f32 %0, %1;" : "=f"(t) : "f"(u));
    return fmaf(0.5f, t, 0.5f);
}

__global__ __launch_bounds__(TPB)
void latent_fused(const float* __restrict__ z, const float* __restrict__ mu,
                  const float* __restrict__ pi, const int* __restrict__ A,
                  const int* __restrict__ B, float* __restrict__ out) {
    __shared__ __align__(16) float s_muT[NC * PITCH];   // [c][d]
    __shared__ float  s_G[NC * NC];
    __shared__ float4 s_c4[NSP];          // {gbb, cab, rinv, sd}
    __shared__ float2 s_cc[NSP];          // {lc, ab-as-int}
    __shared__ float  s_red[TPB];
    __shared__ float4 s_z4[WPB][16];
    __shared__ float  s_dz[WPB][NC];
    __shared__ double s_wsum[WPB];
    __shared__ double s_fin[TPB];
    __shared__ int    s_islast;

    const float LOG2PI = 1.8378770664093453f;
    const float BASE   = -32.0f * LOG2PI;

    int t = threadIdx.x, w = t >> 5, lane = t & 31;
    int item = blockIdx.x * WPB + w;

    // ---- early z load (lanes 0..15, float4) ----
    const float4* zp4 = (const float4*)(z + item * D);
    float4 zv = make_float4(0.f, 0.f, 0.f, 0.f);
    if (lane < 16) zv = zp4[lane];

    // ---- stage mu transposed (1 LDG.128 per thread) + state meta ----
    {
        float4 mv = ((const float4*)mu)[t];     // elements 4t..4t+3
        int d = t >> 2, cb = (t & 3) * 4;
        s_muT[(cb + 0) * PITCH + d] = mv.x;
        s_muT[(cb + 1) * PITCH + d] = mv.y;
        s_muT[(cb + 2) * PITCH + d] = mv.z;
        s_muT[(cb + 3) * PITCH + d] = mv.w;
    }
    float piv = 0.f; int sa = 0, sb = 0;
    if (t < NS) { sa = A[t]; sb = B[t]; piv = pi[t]; }
    s_red[t] = (t < NS) ? __expf(piv) : 0.f;
    if (lane < 16) s_z4[w][lane] = zv;
    __syncthreads();

    // ---- gram: thread t -> pair (ga = t&15, gb = t>>4) ----
    {
        int ga = t & 15, gb = t >> 4;
        const float4* ra = (const float4*)(s_muT + ga * PITCH);
        const float4* rb = (const float4*)(s_muT + gb * PITCH);
        float g0 = 0.f, g1 = 0.f;
        #pragma unroll
        for (int i = 0; i < 16; i++) {
            float4 x = ra[i], y = rb[i];
            g0 = fmaf(x.x, y.x, g0); g0 = fmaf(x.y, y.y, g0);
            g1 = fmaf(x.z, y.z, g1); g1 = fmaf(x.w, y.w, g1);
        }
        s_G[t] = g0 + g1;
    }
    __syncthreads();

    // ---- per-state constants (transcendentals hoisted) ----
    if (t < NSP) {
        float ps = 0.f;
        #pragma unroll
        for (int i = 0; i < TPB / 32; i++) ps += s_red[lane + 32 * i];
        #pragma unroll
        for (int off = 16; off; off >>= 1)
            ps += __shfl_xor_sync(0xffffffffu, ps, off);

        if (t < NS) {
            float gaa = s_G[sa * NC + sa];
            float gbb = s_G[sb * NC + sb];
            float gab = s_G[sb * NC + sa];
            float invsig = fmaf(-2.f, gab, gbb) + gaa;   // exact 0 when sa==sb
            float cab    = gbb - gab;
            float lpi    = __logf(__expf(piv) / ps + 1e-12f);
            float rinv, sd, lc;
            if (invsig == 0.f) {
                rinv = 0.f; sd = 0.f;
                lc = BASE + lpi - __logf(1e-12f);        // cancels runtime *(1e-12)
            } else {
                rinv = 1.0f / invsig;
                sd   = sqrtf(invsig + 1e-12f);
                lc   = BASE + lpi + 0.5f * (LOG2PI - __logf(invsig + 1e-12f));
            }
            s_c4[t] = make_float4(gbb, cab, rinv, sd);
            s_cc[t] = make_float2(lc, __int_as_float(sa | (sb << 8)));
        } else {
            s_c4[t] = make_float4(0.f, 0.f, 0.f, 0.f);
            s_cc[t] = make_float2(-1e30f, __int_as_float(0));
        }
    }

    // ---- zn = |z|^2 ----
    float zn = fmaf(zv.x, zv.x, fmaf(zv.y, zv.y, fmaf(zv.z, zv.z, zv.w * zv.w)));
    #pragma unroll
    for (int off = 16; off; off >>= 1)
        zn += __shfl_xor_sync(0xffffffffu, zn, off);
    __syncthreads();

    // ---- dot: lane (c = lane&15, h = lane>>4) covers dims [h*32, h*32+32) ----
    int c = lane & 15, h = lane >> 4;
    {
        float a0 = 0.f, a1 = 0.f;
        const float4* mt = (const float4*)(s_muT + c * PITCH) + h * 8;
        const float4* zt = &s_z4[w][h * 8];
        #pragma unroll
        for (int i = 0; i < 8; i++) {
            float4 mm = mt[i], zz = zt[i];
            a0 = fmaf(mm.x, zz.x, a0); a0 = fmaf(mm.y, zz.y, a0);
            a1 = fmaf(mm.z, zz.z, a1); a1 = fmaf(mm.w, zz.w, a1);
        }
        float dv = a0 + a1;
        dv += __shfl_xor_sync(0xffffffffu, dv, 16);
        if (lane < NC) s_dz[w][lane] = dv;
    }
    __syncwarp();

    // ---- 5 states per lane: g = lc - 0.5*t2, cd = cdf-diff (no per-state log) ----
    float g[5], cd[5];
    #pragma unroll
    for (int k = 0; k < 5; k++) {
        int s = lane + 32 * k;
        float4 cc = s_c4[s];              // {gbb, cab, rinv, sd}
        float2 c2 = s_cc[s];              // {lc, ab}
        int ab = __float_as_int(c2.y);
        float dzA = s_dz[w][ab & 255];
        float dzB = s_dz[w][ab >> 8];
        float sq    = fmaf(-2.f, dzB, zn) + cc.x;
        float dot12 = (dzB - dzA) - cc.y;
        float mu_   = -dot12 * cc.z;
        float t2    = fmaf(dot12, mu_, sq);
        g[k]  = fmaf(-0.5f, t2, c2.x);
        float d01 = fast_ndtr((1.f - mu_) * cc.w) - fast_ndtr(-mu_ * cc.w);
        cd[k] = fmaxf(d01, 0.f) + 1e-12f;
    }

    // global max of g across warp (cheap: no exp in merge)
    float m = fmaxf(fmaxf(fmaxf(g[0], g[1]), fmaxf(g[2], g[3])), g[4]);
    #pragma unroll
    for (int off = 16; off; off >>= 1)
        m = fmaxf(m, __shfl_xor_sync(0xffffffffu, m, off));

    // acc = sum exp(g - m) * cd   (terms in (0, 1]; max-g term >= 1e-12)
    float acc = 0.f;
    #pragma unroll
    for (int k = 0; k < 5; k++)
        acc = fmaf(__expf(g[k] - m), cd[k], acc);
    #pragma unroll
    for (int off = 16; off; off >>= 1)
        acc += __shfl_xor_sync(0xffffffffu, acc, off);

    if (lane == 0) s_wsum[w] = (double)(m + __logf(acc));
    __syncthreads();

    // ---- deterministic last-block finalize ----
    if (t == 0) {
        double ssum = 0.0;
        #pragma unroll
        for (int i = 0; i < WPB; i++) ssum += s_wsum[i];
        g_partial[blockIdx.x] = ssum;
        __threadfence();
        unsigned int tick = atomicAdd(&g_count, 1u);
        s_islast = (tick == NB - 1u);
    }
    __syncthreads();

    if (s_islast) {
        double vv = 0.0;
        for (int i = t; i < NB; i += TPB) vv += g_partial[i];
        s_fin[t] = vv;
        __syncthreads();
        #pragma unroll
        for (int off = TPB / 2; off > 0; off >>= 1) {
            if (t < off) s_fin[t] += s_fin[t + off];
            __syncthreads();
        }
        if (t == 0) {
            out[0] = (float)(s_fin[0] / (double)NITEMS);
            g_count = 0;   // reset for next graph replay
        }
    }
}

extern "C" void kernel_launch(void* const* d_in, const int* in_sizes, int n_in,
                              void* d_out, int out_size) {
    const float* z  = (const float*)d_in[0];
    const float* mu = (const float*)d_in[1];
    const float* pi = (const float*)d_in[2];
    const int*   A  = (const int*)d_in[3];
    const int*   B  = (const int*)d_in[4];
    float* out = (float*)d_out;
    (void)in_sizes; (void)n_in; (void)out_size;

    latent_fused<<<NB, TPB>>>(z, mu, pi, A, B, out);
}